// round 6
// baseline (speedup 1.0000x reference)
#include <cuda_runtime.h>
#include <cuda_bf16.h>
#include <math.h>
#include <stdint.h>

#define D_MODEL 1024
#define D_FF    3072
#define NH      16
#define DH      64
#define SEQ     2048
#define BATCH   2
#define ROWS    (BATCH*SEQ)   // 4096
#define WINDOW  128

// ---------------- scratch ----------------
__device__ float g_qkv[ROWS * 3 * D_MODEL];
__device__ float g_x2 [ROWS * D_MODEL];
__device__ __nv_bfloat16 g_hh [ROWS * D_MODEL];   // LN out hi
__device__ __nv_bfloat16 g_hl [ROWS * D_MODEL];   // LN out lo
__device__ __nv_bfloat16 g_ch [ROWS * D_MODEL];   // ctx hi
__device__ __nv_bfloat16 g_cl [ROWS * D_MODEL];   // ctx lo
__device__ __nv_bfloat16 g_ffh[ROWS * D_FF];      // gelu(ff1) hi
__device__ __nv_bfloat16 g_ffl[ROWS * D_FF];      // gelu(ff1) lo

// transposed + bf16-split weights: [N][K] layout
#define WT_TOTAL 10485760
__device__ __nv_bfloat16 g_wh[WT_TOTAL];
__device__ __nv_bfloat16 g_wl[WT_TOTAL];

// ---------------- PTX helpers ----------------
__device__ __forceinline__ uint32_t smem_u32(const void* p) {
    uint32_t a;
    asm("{ .reg .u64 t; cvta.to.shared.u64 t, %1; cvt.u32.u64 %0, t; }" : "=r"(a) : "l"(p));
    return a;
}

#define CP16(dst, src) \
    asm volatile("cp.async.cg.shared.global [%0], [%1], 16;" :: "r"(dst), "l"(src) : "memory")
#define CP_COMMIT() asm volatile("cp.async.commit_group;" ::: "memory")
#define CP_WAIT2()  asm volatile("cp.async.wait_group 2;" ::: "memory")

#define LDSM4(R, a) \
    asm volatile("ldmatrix.sync.aligned.m8n8.x4.shared.b16 {%0,%1,%2,%3}, [%4];" \
        : "=r"((R)[0]), "=r"((R)[1]), "=r"((R)[2]), "=r"((R)[3]) : "r"(a))

#define MMA_BF16(d, a, b) \
    asm volatile("mma.sync.aligned.m16n8k16.row.col.f32.bf16.bf16.f32 " \
        "{%0,%1,%2,%3}, {%4,%5,%6,%7}, {%8,%9}, {%0,%1,%2,%3};" \
        : "+f"((d)[0]), "+f"((d)[1]), "+f"((d)[2]), "+f"((d)[3]) \
        : "r"((a)[0]), "r"((a)[1]), "r"((a)[2]), "r"((a)[3]), \
          "r"((b)[0]), "r"((b)[1]))

__device__ __forceinline__ uint32_t pack_bf2(float x, float y) {
    __nv_bfloat16 a = __float2bfloat16_rn(x);
    __nv_bfloat16 b = __float2bfloat16_rn(y);
    return (uint32_t)__bfloat16_as_ushort(a) | ((uint32_t)__bfloat16_as_ushort(b) << 16);
}
__device__ __forceinline__ float gelu_exact(float v) {
    return 0.5f * v * (1.0f + erff(v * 0.70710678118654752f));
}

// ---------------- weight prep: W[K][N] fp32 -> Wt_hi/lo[N][K] bf16 ----------------
__global__ void prep_w(const float* __restrict__ W, __nv_bfloat16* __restrict__ Wh,
                       __nv_bfloat16* __restrict__ Wl, int K, int N) {
    __shared__ float t[32][33];
    int k0 = blockIdx.y * 32, n0 = blockIdx.x * 32;
    int tid = threadIdx.x;
    #pragma unroll
    for (int i = 0; i < 4; i++) {
        int lin = tid + 256 * i;
        int r = lin >> 5, c = lin & 31;
        t[r][c] = W[(size_t)(k0 + r) * N + n0 + c];
    }
    __syncthreads();
    #pragma unroll
    for (int i = 0; i < 4; i++) {
        int lin = tid + 256 * i;
        int n = lin >> 5, k = lin & 31;
        float x = t[k][n];
        __nv_bfloat16 hi = __float2bfloat16_rn(x);
        __nv_bfloat16 lo = __float2bfloat16_rn(x - __bfloat162float(hi));
        size_t o = (size_t)(n0 + n) * K + k0 + k;
        Wh[o] = hi;
        Wl[o] = lo;
    }
}

// ---------------- LayerNorm -> split bf16 ----------------
__global__ void ln_split(const float* __restrict__ x, const float* __restrict__ g,
                         const float* __restrict__ bb,
                         __nv_bfloat16* __restrict__ oh, __nv_bfloat16* __restrict__ ol) {
    int row = blockIdx.x;
    const float* xr = x + (size_t)row * D_MODEL;
    int tid = threadIdx.x;
    float4 v = ((const float4*)xr)[tid];
    float s  = v.x + v.y + v.z + v.w;
    float s2 = v.x*v.x + v.y*v.y + v.z*v.z + v.w*v.w;
    __shared__ float rs[8], rs2[8];
    #pragma unroll
    for (int o = 16; o > 0; o >>= 1) {
        s  += __shfl_xor_sync(0xffffffffu, s,  o);
        s2 += __shfl_xor_sync(0xffffffffu, s2, o);
    }
    int w = tid >> 5, l = tid & 31;
    if (l == 0) { rs[w] = s; rs2[w] = s2; }
    __syncthreads();
    float ts = 0.f, ts2 = 0.f;
    #pragma unroll
    for (int i = 0; i < 8; i++) { ts += rs[i]; ts2 += rs2[i]; }
    float mu  = ts * (1.0f / D_MODEL);
    float var = ts2 * (1.0f / D_MODEL) - mu * mu;
    float inv = rsqrtf(var + 1e-5f);
    float4 gg = ((const float4*)g)[tid];
    float4 bv = ((const float4*)bb)[tid];
    float o0 = (v.x - mu) * inv * gg.x + bv.x;
    float o1 = (v.y - mu) * inv * gg.y + bv.y;
    float o2 = (v.z - mu) * inv * gg.z + bv.z;
    float o3 = (v.w - mu) * inv * gg.w + bv.w;
    float h0 = __bfloat162float(__float2bfloat16_rn(o0));
    float h1 = __bfloat162float(__float2bfloat16_rn(o1));
    float h2 = __bfloat162float(__float2bfloat16_rn(o2));
    float h3 = __bfloat162float(__float2bfloat16_rn(o3));
    size_t base = (size_t)row * D_MODEL + tid * 4;
    uint2 hv = {pack_bf2(o0, o1), pack_bf2(o2, o3)};
    uint2 lv = {pack_bf2(o0 - h0, o1 - h1), pack_bf2(o2 - h2, o3 - h3)};
    *(uint2*)&oh[base] = hv;
    *(uint2*)&ol[base] = lv;
}

// ---------------- bf16x3 pipelined mma GEMM ----------------
// C(M,N) = A(M,K) @ B(K,N):  A split bf16 [M][K], B split bf16 [N][K].
// C ≈ Ah*Bh + Ah*Bl + Al*Bh (fp32 accum).
// CTA 256x128, BK=32, 8 warps (4m x 2n), warp tile 64x64.
// 3-stage cp.async pipeline, ldmatrix fragments.
// SMEM stage (bytes): AH 0 (20480), AL 20480, BH 40960 (10240), BL 51200; stride 61440.

#define ST_STRIDE 61440u
#define GEMM_SMEM (3 * 61440)

template<int EPI>  // 0: Cf=acc+bias  1: Cf=acc+bias+res  2: split(gelu(acc+bias))->Ch,Cl
__global__ void __launch_bounds__(256, 1) gemm_mma(
    const __nv_bfloat16* __restrict__ Ah, const __nv_bfloat16* __restrict__ Al,
    const __nv_bfloat16* __restrict__ Bh, const __nv_bfloat16* __restrict__ Bl,
    const float* __restrict__ bias, const float* __restrict__ res,
    float* __restrict__ Cf, __nv_bfloat16* __restrict__ Ch, __nv_bfloat16* __restrict__ Cl,
    int M, int N, int K)
{
    extern __shared__ __align__(16) __nv_bfloat16 smg[];
    uint32_t sbase = smem_u32(smg);
    int tid = threadIdx.x, wid = tid >> 5, lane = tid & 31;
    int g = lane >> 2, tg = lane & 3;
    int wm = wid >> 1, wn = wid & 1;
    int bm = blockIdx.y * 256, bn = blockIdx.x * 128;
    int ns = K >> 5;

    // ldmatrix lane address components
    int lt = lane >> 3;
    int arow_l = (lt & 1) * 8 + (lane & 7);
    int ak_l   = (lt >> 1) * 8;
    int brow_l = (lt >> 1) * 8 + (lane & 7);
    int bk_l   = (lt & 1) * 8;

    // cp.async per-thread mapping
    int lrow = tid >> 2, lkc = tid & 3;
    const __nv_bfloat16* gAh = Ah + (size_t)(bm + lrow) * K + lkc * 8;
    const __nv_bfloat16* gAl = Al + (size_t)(bm + lrow) * K + lkc * 8;
    const __nv_bfloat16* gBh = Bh + (size_t)(bn + lrow) * K + lkc * 8;
    const __nv_bfloat16* gBl = Bl + (size_t)(bn + lrow) * K + lkc * 8;
    uint32_t sA = (uint32_t)(lrow * 40 + lkc * 8) * 2;

    float acc[4][8][4];
    #pragma unroll
    for (int mi = 0; mi < 4; mi++)
        #pragma unroll
        for (int ni = 0; ni < 8; ni++)
            #pragma unroll
            for (int q = 0; q < 4; q++) acc[mi][ni][q] = 0.f;

    // ---- prologue: issue stages 0..2 ----
    #pragma unroll
    for (int p = 0; p < 3; p++) {
        if (p < ns) {
            uint32_t so = sbase + (uint32_t)p * ST_STRIDE;
            int k0 = p << 5;
            #pragma unroll
            for (int i = 0; i < 4; i++) {
                CP16(so + sA + i * 5120u,          gAh + k0 + (size_t)i * 64 * K);
                CP16(so + 20480u + sA + i * 5120u, gAl + k0 + (size_t)i * 64 * K);
            }
            #pragma unroll
            for (int i = 0; i < 2; i++) {
                CP16(so + 40960u + sA + i * 5120u, gBh + k0 + (size_t)i * 64 * K);
                CP16(so + 51200u + sA + i * 5120u, gBl + k0 + (size_t)i * 64 * K);
            }
        }
        CP_COMMIT();
    }

    int slot = 0;
    for (int s = 0; s < ns; s++) {
        CP_WAIT2();
        __syncthreads();

        uint32_t st = sbase + (uint32_t)slot * ST_STRIDE;
        #pragma unroll
        for (int ks = 0; ks < 2; ks++) {
            int ks16 = ks * 16;
            uint32_t ah[4][4], al[4][4], bh[8][2], bl[8][2];
            #pragma unroll
            for (int mi = 0; mi < 4; mi++) {
                uint32_t ao = st + (uint32_t)((wm * 64 + mi * 16 + arow_l) * 40 + ks16 + ak_l) * 2;
                LDSM4(ah[mi], ao);
                LDSM4(al[mi], ao + 20480u);
            }
            #pragma unroll
            for (int nb = 0; nb < 4; nb++) {
                uint32_t bo = st + 40960u +
                    (uint32_t)((wn * 64 + nb * 16 + brow_l) * 40 + ks16 + bk_l) * 2;
                uint32_t r[4], q[4];
                LDSM4(r, bo);
                LDSM4(q, bo + 10240u);
                bh[2*nb][0] = r[0]; bh[2*nb][1] = r[1];
                bh[2*nb+1][0] = r[2]; bh[2*nb+1][1] = r[3];
                bl[2*nb][0] = q[0]; bl[2*nb][1] = q[1];
                bl[2*nb+1][0] = q[2]; bl[2*nb+1][1] = q[3];
            }
            #pragma unroll
            for (int mi = 0; mi < 4; mi++)
                #pragma unroll
                for (int ni = 0; ni < 8; ni++)
                    MMA_BF16(acc[mi][ni], ah[mi], bh[ni]);
            #pragma unroll
            for (int mi = 0; mi < 4; mi++)
                #pragma unroll
                for (int ni = 0; ni < 8; ni++)
                    MMA_BF16(acc[mi][ni], ah[mi], bl[ni]);
            #pragma unroll
            for (int mi = 0; mi < 4; mi++)
                #pragma unroll
                for (int ni = 0; ni < 8; ni++)
                    MMA_BF16(acc[mi][ni], al[mi], bh[ni]);
        }
        __syncthreads();

        // refill this slot with stage s+3
        if (s + 3 < ns) {
            uint32_t so = sbase + (uint32_t)slot * ST_STRIDE;
            int k0 = (s + 3) << 5;
            #pragma unroll
            for (int i = 0; i < 4; i++) {
                CP16(so + sA + i * 5120u,          gAh + k0 + (size_t)i * 64 * K);
                CP16(so + 20480u + sA + i * 5120u, gAl + k0 + (size_t)i * 64 * K);
            }
            #pragma unroll
            for (int i = 0; i < 2; i++) {
                CP16(so + 40960u + sA + i * 5120u, gBh + k0 + (size_t)i * 64 * K);
                CP16(so + 51200u + sA + i * 5120u, gBl + k0 + (size_t)i * 64 * K);
            }
        }
        CP_COMMIT();
        slot = (slot == 2) ? 0 : slot + 1;
    }

    // ---- epilogue ----
    #pragma unroll
    for (int mi = 0; mi < 4; mi++) {
        int r0 = bm + wm * 64 + mi * 16 + g;
        int r1 = r0 + 8;
        #pragma unroll
        for (int ni = 0; ni < 8; ni++) {
            int cn = bn + wn * 64 + ni * 8 + tg * 2;
            float2 bv = *(const float2*)&bias[cn];
            float x0 = acc[mi][ni][0] + bv.x;
            float x1 = acc[mi][ni][1] + bv.y;
            float x2 = acc[mi][ni][2] + bv.x;
            float x3 = acc[mi][ni][3] + bv.y;
            size_t o0 = (size_t)r0 * N + cn;
            size_t o1 = (size_t)r1 * N + cn;
            if (EPI == 1) {
                float2 q0 = *(const float2*)&res[o0];
                float2 q1 = *(const float2*)&res[o1];
                x0 += q0.x; x1 += q0.y; x2 += q1.x; x3 += q1.y;
            }
            if (EPI == 2) {
                x0 = gelu_exact(x0); x1 = gelu_exact(x1);
                x2 = gelu_exact(x2); x3 = gelu_exact(x3);
                float h0 = __bfloat162float(__float2bfloat16_rn(x0));
                float h1 = __bfloat162float(__float2bfloat16_rn(x1));
                float h2 = __bfloat162float(__float2bfloat16_rn(x2));
                float h3 = __bfloat162float(__float2bfloat16_rn(x3));
                *(uint32_t*)&Ch[o0] = pack_bf2(x0, x1);
                *(uint32_t*)&Ch[o1] = pack_bf2(x2, x3);
                *(uint32_t*)&Cl[o0] = pack_bf2(x0 - h0, x1 - h1);
                *(uint32_t*)&Cl[o1] = pack_bf2(x2 - h2, x3 - h3);
            } else {
                float2 s0 = {x0, x1}, s1 = {x2, x3};
                *(float2*)&Cf[o0] = s0;
                *(float2*)&Cf[o1] = s1;
            }
        }
    }
}

// ---------------- sliding-window attention (verified; now writes split ctx) ----------------
#define QT   64
#define KT   192
#define SPAD 65
#define SSP  196

__global__ void attn_kernel(const float* __restrict__ qkv,
                            __nv_bfloat16* __restrict__ ch,
                            __nv_bfloat16* __restrict__ cl) {
    extern __shared__ float smf[];
    float* qs = smf;
    float* ks = smf + QT * SPAD;
    float* vs = ks + KT * SPAD;
    float* ss = smf;

    int tid = threadIdx.x;
    int tx = tid & 15, ty = tid >> 4;
    int q0 = blockIdx.x * QT;
    int h  = blockIdx.y;
    int b  = blockIdx.z;
    int k0 = q0 - WINDOW;
    const float* base = qkv + (size_t)b * SEQ * (3 * D_MODEL);

    for (int i = tid; i < QT * DH; i += 256) {
        int r = i / DH, d = i % DH;
        qs[r * SPAD + d] = base[(size_t)(q0 + r) * (3 * D_MODEL) + h * DH + d];
    }
    for (int i = tid; i < KT * DH; i += 256) {
        int r = i / DH, d = i % DH;
        int kj = k0 + r;
        float kv = 0.f, vv = 0.f;
        if (kj >= 0) {
            const float* rowp = base + (size_t)kj * (3 * D_MODEL);
            kv = rowp[D_MODEL     + h * DH + d];
            vv = rowp[2 * D_MODEL + h * DH + d];
        }
        ks[r * SPAD + d] = kv;
        vs[r * SPAD + d] = vv;
    }
    __syncthreads();

    float sc[4][12];
    #pragma unroll
    for (int i = 0; i < 4; i++)
        #pragma unroll
        for (int jj = 0; jj < 12; jj++) sc[i][jj] = 0.f;

    for (int d = 0; d < DH; d++) {
        float a[4], bb[12];
        #pragma unroll
        for (int i = 0; i < 4; i++) a[i] = qs[(ty * 4 + i) * SPAD + d];
        #pragma unroll
        for (int jj = 0; jj < 12; jj++) bb[jj] = ks[(tx * 12 + jj) * SPAD + d];
        #pragma unroll
        for (int i = 0; i < 4; i++)
            #pragma unroll
            for (int jj = 0; jj < 12; jj++)
                sc[i][jj] += a[i] * bb[jj];
    }

    float invsum[4];
    #pragma unroll
    for (int i = 0; i < 4; i++) {
        int q = ty * 4 + i;
        float mx = -3.4e38f;
        #pragma unroll
        for (int jj = 0; jj < 12; jj++) {
            int j = tx * 12 + jj;
            bool ok = (j > q) && (j <= q + WINDOW) && (k0 + j >= 0);
            float sv = ok ? sc[i][jj] * 0.125f : -3.4e38f;
            sc[i][jj] = sv;
            mx = fmaxf(mx, sv);
        }
        #pragma unroll
        for (int o = 1; o < 16; o <<= 1)
            mx = fmaxf(mx, __shfl_xor_sync(0xffffffffu, mx, o));
        float su = 0.f;
        #pragma unroll
        for (int jj = 0; jj < 12; jj++) {
            float p = (sc[i][jj] > -1e37f) ? __expf(sc[i][jj] - mx) : 0.f;
            sc[i][jj] = p;
            su += p;
        }
        #pragma unroll
        for (int o = 1; o < 16; o <<= 1)
            su += __shfl_xor_sync(0xffffffffu, su, o);
        invsum[i] = 1.0f / su;
    }

    __syncthreads();
    #pragma unroll
    for (int i = 0; i < 4; i++)
        #pragma unroll
        for (int jj = 0; jj < 12; jj++)
            ss[(ty * 4 + i) * SSP + tx * 12 + jj] = sc[i][jj] * invsum[i];
    __syncthreads();

    float o[4][4];
    #pragma unroll
    for (int i = 0; i < 4; i++)
        #pragma unroll
        for (int l = 0; l < 4; l++) o[i][l] = 0.f;

    for (int j = 0; j < KT; j++) {
        float a[4], bv[4];
        #pragma unroll
        for (int i = 0; i < 4; i++) a[i] = ss[(ty * 4 + i) * SSP + j];
        #pragma unroll
        for (int l = 0; l < 4; l++) bv[l] = vs[j * SPAD + tx * 4 + l];
        #pragma unroll
        for (int i = 0; i < 4; i++)
            #pragma unroll
            for (int l = 0; l < 4; l++)
                o[i][l] += a[i] * bv[l];
    }
    #pragma unroll
    for (int i = 0; i < 4; i++) {
        size_t ro = (size_t)(b * SEQ + q0 + ty * 4 + i) * D_MODEL + h * DH + tx * 4;
        float h0 = __bfloat162float(__float2bfloat16_rn(o[i][0]));
        float h1 = __bfloat162float(__float2bfloat16_rn(o[i][1]));
        float h2 = __bfloat162float(__float2bfloat16_rn(o[i][2]));
        float h3 = __bfloat162float(__float2bfloat16_rn(o[i][3]));
        *(uint32_t*)&ch[ro]     = pack_bf2(o[i][0], o[i][1]);
        *(uint32_t*)&ch[ro + 2] = pack_bf2(o[i][2], o[i][3]);
        *(uint32_t*)&cl[ro]     = pack_bf2(o[i][0] - h0, o[i][1] - h1);
        *(uint32_t*)&cl[ro + 2] = pack_bf2(o[i][2] - h2, o[i][3] - h3);
    }
}

// ---------------- launcher ----------------
extern "C" void kernel_launch(void* const* d_in, const int* in_sizes, int n_in,
                              void* d_out, int out_size) {
    const float* x     = (const float*)d_in[0];
    const float* w_qkv = (const float*)d_in[1];
    const float* b_qkv = (const float*)d_in[2];
    const float* w_out = (const float*)d_in[3];
    const float* b_out = (const float*)d_in[4];
    const float* w_ff1 = (const float*)d_in[5];
    const float* b_ff1 = (const float*)d_in[6];
    const float* w_ff2 = (const float*)d_in[7];
    const float* b_ff2 = (const float*)d_in[8];
    const float* ln1_g = (const float*)d_in[9];
    const float* ln1_b = (const float*)d_in[10];
    const float* ln2_g = (const float*)d_in[11];
    const float* ln2_b = (const float*)d_in[12];
    float* out = (float*)d_out;

    float *qkv, *x2;
    __nv_bfloat16 *hh, *hl, *ch, *cl, *ffh, *ffl, *wh, *wl;
    cudaGetSymbolAddress((void**)&qkv, g_qkv);
    cudaGetSymbolAddress((void**)&x2,  g_x2);
    cudaGetSymbolAddress((void**)&hh,  g_hh);
    cudaGetSymbolAddress((void**)&hl,  g_hl);
    cudaGetSymbolAddress((void**)&ch,  g_ch);
    cudaGetSymbolAddress((void**)&cl,  g_cl);
    cudaGetSymbolAddress((void**)&ffh, g_ffh);
    cudaGetSymbolAddress((void**)&ffl, g_ffl);
    cudaGetSymbolAddress((void**)&wh,  g_wh);
    cudaGetSymbolAddress((void**)&wl,  g_wl);

    __nv_bfloat16 *wh_qkv = wh,           *wl_qkv = wl;
    __nv_bfloat16 *wh_out = wh + 3145728, *wl_out = wl + 3145728;
    __nv_bfloat16 *wh_ff1 = wh + 4194304, *wl_ff1 = wl + 4194304;
    __nv_bfloat16 *wh_ff2 = wh + 7340032, *wl_ff2 = wl + 7340032;

    cudaFuncSetAttribute(gemm_mma<0>, cudaFuncAttributeMaxDynamicSharedMemorySize, GEMM_SMEM);
    cudaFuncSetAttribute(gemm_mma<1>, cudaFuncAttributeMaxDynamicSharedMemorySize, GEMM_SMEM);
    cudaFuncSetAttribute(gemm_mma<2>, cudaFuncAttributeMaxDynamicSharedMemorySize, GEMM_SMEM);

    // 0. weight prep (transpose + bf16 split)
    prep_w<<<dim3(3 * D_MODEL / 32, D_MODEL / 32), 256>>>(w_qkv, wh_qkv, wl_qkv, D_MODEL, 3 * D_MODEL);
    prep_w<<<dim3(D_MODEL / 32, D_MODEL / 32), 256>>>(w_out, wh_out, wl_out, D_MODEL, D_MODEL);
    prep_w<<<dim3(D_FF / 32, D_MODEL / 32), 256>>>(w_ff1, wh_ff1, wl_ff1, D_MODEL, D_FF);
    prep_w<<<dim3(D_MODEL / 32, D_FF / 32), 256>>>(w_ff2, wh_ff2, wl_ff2, D_FF, D_MODEL);

    // 1. LN1 -> split
    ln_split<<<ROWS, 256>>>(x, ln1_g, ln1_b, hh, hl);

    // 2. QKV projection (fp32 out)
    gemm_mma<0><<<dim3(3 * D_MODEL / 128, ROWS / 256), 256, GEMM_SMEM>>>(
        hh, hl, wh_qkv, wl_qkv, b_qkv, nullptr, qkv, nullptr, nullptr,
        ROWS, 3 * D_MODEL, D_MODEL);

    // 3. attention -> split ctx
    size_t smem = (size_t)(QT * SPAD + 2 * KT * SPAD) * sizeof(float);
    cudaFuncSetAttribute(attn_kernel, cudaFuncAttributeMaxDynamicSharedMemorySize, (int)smem);
    attn_kernel<<<dim3(SEQ / QT, NH, BATCH), 256, smem>>>(qkv, ch, cl);

    // 4. out-projection + residual (fp32 out)
    gemm_mma<1><<<dim3(D_MODEL / 128, ROWS / 256), 256, GEMM_SMEM>>>(
        ch, cl, wh_out, wl_out, b_out, x, x2, nullptr, nullptr,
        ROWS, D_MODEL, D_MODEL);

    // 5. LN2 -> split
    ln_split<<<ROWS, 256>>>(x2, ln2_g, ln2_b, hh, hl);

    // 6. FF1 + gelu -> split ff
    gemm_mma<2><<<dim3(D_FF / 128, ROWS / 256), 256, GEMM_SMEM>>>(
        hh, hl, wh_ff1, wl_ff1, b_ff1, nullptr, nullptr, ffh, ffl,
        ROWS, D_FF, D_MODEL);

    // 7. FF2 + residual -> output
    gemm_mma<1><<<dim3(D_MODEL / 128, ROWS / 256), 256, GEMM_SMEM>>>(
        ffh, ffl, wh_ff2, wl_ff2, b_ff2, x2, out, nullptr, nullptr,
        ROWS, D_MODEL, D_FF);
}

// round 9
// speedup vs baseline: 1.4346x; 1.4346x over previous
#include <cuda_runtime.h>
#include <cuda_bf16.h>
#include <math.h>
#include <stdint.h>

#define D_MODEL 1024
#define D_FF    3072
#define NH      16
#define DH      64
#define SEQ     2048
#define BATCH   2
#define ROWS    (BATCH*SEQ)   // 4096
#define WINDOW  128

// ---------------- scratch ----------------
__device__ float g_qkv[ROWS * 3 * D_MODEL];
__device__ float g_x2 [ROWS * D_MODEL];
__device__ __nv_bfloat16 g_hh [ROWS * D_MODEL];
__device__ __nv_bfloat16 g_hl [ROWS * D_MODEL];
__device__ __nv_bfloat16 g_ch [ROWS * D_MODEL];
__device__ __nv_bfloat16 g_cl [ROWS * D_MODEL];
__device__ __nv_bfloat16 g_ffh[ROWS * D_FF];
__device__ __nv_bfloat16 g_ffl[ROWS * D_FF];

#define WT_TOTAL 10485760
__device__ __nv_bfloat16 g_wh[WT_TOTAL];
__device__ __nv_bfloat16 g_wl[WT_TOTAL];

// ---------------- PTX helpers ----------------
__device__ __forceinline__ uint32_t smem_u32(const void* p) {
    uint32_t a;
    asm("{ .reg .u64 t; cvta.to.shared.u64 t, %1; cvt.u32.u64 %0, t; }" : "=r"(a) : "l"(p));
    return a;
}
#define CP16(dst, src) \
    asm volatile("cp.async.cg.shared.global [%0], [%1], 16;" :: "r"(dst), "l"(src) : "memory")
#define CP_COMMIT() asm volatile("cp.async.commit_group;" ::: "memory")
#define CP_WAIT2()  asm volatile("cp.async.wait_group 2;" ::: "memory")

#define LDSM4(R, a) \
    asm volatile("ldmatrix.sync.aligned.m8n8.x4.shared.b16 {%0,%1,%2,%3}, [%4];" \
        : "=r"((R)[0]), "=r"((R)[1]), "=r"((R)[2]), "=r"((R)[3]) : "r"(a))

#define MMA_BF16(d, a, b) \
    asm volatile("mma.sync.aligned.m16n8k16.row.col.f32.bf16.bf16.f32 " \
        "{%0,%1,%2,%3}, {%4,%5,%6,%7}, {%8,%9}, {%0,%1,%2,%3};" \
        : "+f"((d)[0]), "+f"((d)[1]), "+f"((d)[2]), "+f"((d)[3]) \
        : "r"((a)[0]), "r"((a)[1]), "r"((a)[2]), "r"((a)[3]), \
          "r"((b)[0]), "r"((b)[1]))

__device__ __forceinline__ uint32_t pack_bf2(float x, float y) {
    __nv_bfloat16 a = __float2bfloat16_rn(x);
    __nv_bfloat16 b = __float2bfloat16_rn(y);
    return (uint32_t)__bfloat16_as_ushort(a) | ((uint32_t)__bfloat16_as_ushort(b) << 16);
}
__device__ __forceinline__ float gelu_exact(float v) {
    return 0.5f * v * (1.0f + erff(v * 0.70710678118654752f));
}

// ---------------- weight prep ----------------
__global__ void prep_w(const float* __restrict__ W, __nv_bfloat16* __restrict__ Wh,
                       __nv_bfloat16* __restrict__ Wl, int K, int N) {
    __shared__ float t[32][33];
    int k0 = blockIdx.y * 32, n0 = blockIdx.x * 32;
    int tid = threadIdx.x;
    #pragma unroll
    for (int i = 0; i < 4; i++) {
        int lin = tid + 256 * i;
        int r = lin >> 5, c = lin & 31;
        t[r][c] = W[(size_t)(k0 + r) * N + n0 + c];
    }
    __syncthreads();
    #pragma unroll
    for (int i = 0; i < 4; i++) {
        int lin = tid + 256 * i;
        int n = lin >> 5, k = lin & 31;
        float x = t[k][n];
        __nv_bfloat16 hi = __float2bfloat16_rn(x);
        __nv_bfloat16 lo = __float2bfloat16_rn(x - __bfloat162float(hi));
        size_t o = (size_t)(n0 + n) * K + k0 + k;
        Wh[o] = hi;
        Wl[o] = lo;
    }
}

// ---------------- LayerNorm -> split bf16 ----------------
__global__ void ln_split(const float* __restrict__ x, const float* __restrict__ g,
                         const float* __restrict__ bb,
                         __nv_bfloat16* __restrict__ oh, __nv_bfloat16* __restrict__ ol) {
    int row = blockIdx.x;
    const float* xr = x + (size_t)row * D_MODEL;
    int tid = threadIdx.x;
    float4 v = ((const float4*)xr)[tid];
    float s  = v.x + v.y + v.z + v.w;
    float s2 = v.x*v.x + v.y*v.y + v.z*v.z + v.w*v.w;
    __shared__ float rs[8], rs2[8];
    #pragma unroll
    for (int o = 16; o > 0; o >>= 1) {
        s  += __shfl_xor_sync(0xffffffffu, s,  o);
        s2 += __shfl_xor_sync(0xffffffffu, s2, o);
    }
    int w = tid >> 5, l = tid & 31;
    if (l == 0) { rs[w] = s; rs2[w] = s2; }
    __syncthreads();
    float ts = 0.f, ts2 = 0.f;
    #pragma unroll
    for (int i = 0; i < 8; i++) { ts += rs[i]; ts2 += rs2[i]; }
    float mu  = ts * (1.0f / D_MODEL);
    float var = ts2 * (1.0f / D_MODEL) - mu * mu;
    float inv = rsqrtf(var + 1e-5f);
    float4 gg = ((const float4*)g)[tid];
    float4 bv = ((const float4*)bb)[tid];
    float o0 = (v.x - mu) * inv * gg.x + bv.x;
    float o1 = (v.y - mu) * inv * gg.y + bv.y;
    float o2 = (v.z - mu) * inv * gg.z + bv.z;
    float o3 = (v.w - mu) * inv * gg.w + bv.w;
    float h0 = __bfloat162float(__float2bfloat16_rn(o0));
    float h1 = __bfloat162float(__float2bfloat16_rn(o1));
    float h2 = __bfloat162float(__float2bfloat16_rn(o2));
    float h3 = __bfloat162float(__float2bfloat16_rn(o3));
    size_t base = (size_t)row * D_MODEL + tid * 4;
    uint2 hv = {pack_bf2(o0, o1), pack_bf2(o2, o3)};
    uint2 lv = {pack_bf2(o0 - h0, o1 - h1), pack_bf2(o2 - h2, o3 - h3)};
    *(uint2*)&oh[base] = hv;
    *(uint2*)&ol[base] = lv;
}

// ---------------- bf16x3 pipelined mma GEMM ----------------
// CTA 128x128, BK=32, 8 warps (4m x 2n), warp tile 32x64.
// 4-stage cp.async; ldmatrix fragments; pre-split bf16 operands.
// Stage layout (bytes): AH 0, AL 10240, BH 20480, BL 30720; stride 40960.

#define ST_STRIDE 40960u
#define GEMM_SMEM (4 * 40960)

template<int EPI>  // 0: Cf=acc+bias  1: +res  2: split(gelu(acc+bias))->Ch,Cl
__global__ void __launch_bounds__(256, 1) gemm_mma(
    const __nv_bfloat16* __restrict__ Ah, const __nv_bfloat16* __restrict__ Al,
    const __nv_bfloat16* __restrict__ Bh, const __nv_bfloat16* __restrict__ Bl,
    const float* __restrict__ bias, const float* __restrict__ res,
    float* __restrict__ Cf, __nv_bfloat16* __restrict__ Ch, __nv_bfloat16* __restrict__ Cl,
    int M, int N, int K)
{
    extern __shared__ __align__(16) __nv_bfloat16 smg[];
    uint32_t sbase = smem_u32(smg);
    int tid = threadIdx.x, wid = tid >> 5, lane = tid & 31;
    int g = lane >> 2, tg = lane & 3;
    int wm = wid >> 1, wn = wid & 1;
    int bm = blockIdx.y * 128, bn = blockIdx.x * 128;
    int ns = K >> 5;

    // ldmatrix lane address components
    int lt = lane >> 3;
    int arow_l = (lt & 1) * 8 + (lane & 7);
    int ak_l   = (lt >> 1) * 8;
    int brow_l = (lt >> 1) * 8 + (lane & 7);
    int bk_l   = (lt & 1) * 8;

    // cp.async mapping: 128 rows x 4 chunks(16B) per tile; 2 chunks per thread
    int lrow = tid >> 1, lkc = (tid & 1) * 2;
    const __nv_bfloat16* gAh = Ah + (size_t)(bm + lrow) * K + lkc * 8;
    const __nv_bfloat16* gAl = Al + (size_t)(bm + lrow) * K + lkc * 8;
    const __nv_bfloat16* gBh = Bh + (size_t)(bn + lrow) * K + lkc * 8;
    const __nv_bfloat16* gBl = Bl + (size_t)(bn + lrow) * K + lkc * 8;
    uint32_t sA = (uint32_t)(lrow * 80 + lkc * 16);

    float acc[2][8][4];
    #pragma unroll
    for (int mi = 0; mi < 2; mi++)
        #pragma unroll
        for (int ni = 0; ni < 8; ni++)
            #pragma unroll
            for (int q = 0; q < 4; q++) acc[mi][ni][q] = 0.f;

    // ---- prologue: stages 0..2 ----
    #pragma unroll
    for (int p = 0; p < 3; p++) {
        uint32_t so = sbase + (uint32_t)p * ST_STRIDE;
        int k0 = p << 5;
        #pragma unroll
        for (int c = 0; c < 2; c++) {
            CP16(so + sA + c * 16u,          gAh + k0 + c * 8);
            CP16(so + 10240u + sA + c * 16u, gAl + k0 + c * 8);
            CP16(so + 20480u + sA + c * 16u, gBh + k0 + c * 8);
            CP16(so + 30720u + sA + c * 16u, gBl + k0 + c * 8);
        }
        CP_COMMIT();
    }

    for (int s = 0; s < ns; s++) {
        CP_WAIT2();
        __syncthreads();

        uint32_t st = sbase + (uint32_t)(s & 3) * ST_STRIDE;
        #pragma unroll
        for (int ks = 0; ks < 2; ks++) {
            int ks16 = ks * 16;
            uint32_t ah[2][4], al[2][4], bh[8][2], bl[8][2];
            #pragma unroll
            for (int mi = 0; mi < 2; mi++) {
                uint32_t ao = st + (uint32_t)((wm * 32 + mi * 16 + arow_l) * 40 + ks16 + ak_l) * 2;
                LDSM4(ah[mi], ao);
                LDSM4(al[mi], ao + 10240u);
            }
            #pragma unroll
            for (int nb = 0; nb < 4; nb++) {
                uint32_t bo = st + 20480u +
                    (uint32_t)((wn * 64 + nb * 16 + brow_l) * 40 + ks16 + bk_l) * 2;
                uint32_t r[4], q[4];
                LDSM4(r, bo);
                LDSM4(q, bo + 10240u);
                bh[2*nb][0] = r[0]; bh[2*nb][1] = r[1];
                bh[2*nb+1][0] = r[2]; bh[2*nb+1][1] = r[3];
                bl[2*nb][0] = q[0]; bl[2*nb][1] = q[1];
                bl[2*nb+1][0] = q[2]; bl[2*nb+1][1] = q[3];
            }
            #pragma unroll
            for (int mi = 0; mi < 2; mi++)
                #pragma unroll
                for (int ni = 0; ni < 8; ni++)
                    MMA_BF16(acc[mi][ni], ah[mi], bh[ni]);
            #pragma unroll
            for (int mi = 0; mi < 2; mi++)
                #pragma unroll
                for (int ni = 0; ni < 8; ni++)
                    MMA_BF16(acc[mi][ni], ah[mi], bl[ni]);
            #pragma unroll
            for (int mi = 0; mi < 2; mi++)
                #pragma unroll
                for (int ni = 0; ni < 8; ni++)
                    MMA_BF16(acc[mi][ni], al[mi], bh[ni]);
        }

        // refill slot (s+3)&3 (drained: last read at stage s-1, barrier above)
        if (s + 3 < ns) {
            uint32_t so = sbase + (uint32_t)((s + 3) & 3) * ST_STRIDE;
            int k0 = (s + 3) << 5;
            #pragma unroll
            for (int c = 0; c < 2; c++) {
                CP16(so + sA + c * 16u,          gAh + k0 + c * 8);
                CP16(so + 10240u + sA + c * 16u, gAl + k0 + c * 8);
                CP16(so + 20480u + sA + c * 16u, gBh + k0 + c * 8);
                CP16(so + 30720u + sA + c * 16u, gBl + k0 + c * 8);
            }
        }
        CP_COMMIT();
    }

    // ---- epilogue ----
    #pragma unroll
    for (int mi = 0; mi < 2; mi++) {
        int r0 = bm + wm * 32 + mi * 16 + g;
        int r1 = r0 + 8;
        #pragma unroll
        for (int ni = 0; ni < 8; ni++) {
            int cn = bn + wn * 64 + ni * 8 + tg * 2;
            float2 bv = *(const float2*)&bias[cn];
            float x0 = acc[mi][ni][0] + bv.x;
            float x1 = acc[mi][ni][1] + bv.y;
            float x2 = acc[mi][ni][2] + bv.x;
            float x3 = acc[mi][ni][3] + bv.y;
            size_t o0 = (size_t)r0 * N + cn;
            size_t o1 = (size_t)r1 * N + cn;
            if (EPI == 1) {
                float2 q0 = *(const float2*)&res[o0];
                float2 q1 = *(const float2*)&res[o1];
                x0 += q0.x; x1 += q0.y; x2 += q1.x; x3 += q1.y;
            }
            if (EPI == 2) {
                x0 = gelu_exact(x0); x1 = gelu_exact(x1);
                x2 = gelu_exact(x2); x3 = gelu_exact(x3);
                float h0 = __bfloat162float(__float2bfloat16_rn(x0));
                float h1 = __bfloat162float(__float2bfloat16_rn(x1));
                float h2 = __bfloat162float(__float2bfloat16_rn(x2));
                float h3 = __bfloat162float(__float2bfloat16_rn(x3));
                *(uint32_t*)&Ch[o0] = pack_bf2(x0, x1);
                *(uint32_t*)&Ch[o1] = pack_bf2(x2, x3);
                *(uint32_t*)&Cl[o0] = pack_bf2(x0 - h0, x1 - h1);
                *(uint32_t*)&Cl[o1] = pack_bf2(x2 - h2, x3 - h3);
            } else {
                float2 s0 = {x0, x1}, s1 = {x2, x3};
                *(float2*)&Cf[o0] = s0;
                *(float2*)&Cf[o1] = s1;
            }
        }
    }
}

// ---------------- sliding-window attention (verified; writes split ctx) ----------------
#define QT   64
#define KT   192
#define SPAD 65
#define SSP  196

__global__ void attn_kernel(const float* __restrict__ qkv,
                            __nv_bfloat16* __restrict__ ch,
                            __nv_bfloat16* __restrict__ cl) {
    extern __shared__ float smf[];
    float* qs = smf;
    float* ks = smf + QT * SPAD;
    float* vs = ks + KT * SPAD;
    float* ss = smf;

    int tid = threadIdx.x;
    int tx = tid & 15, ty = tid >> 4;
    int q0 = blockIdx.x * QT;
    int h  = blockIdx.y;
    int b  = blockIdx.z;
    int k0 = q0 - WINDOW;
    const float* base = qkv + (size_t)b * SEQ * (3 * D_MODEL);

    for (int i = tid; i < QT * DH; i += 256) {
        int r = i / DH, d = i % DH;
        qs[r * SPAD + d] = base[(size_t)(q0 + r) * (3 * D_MODEL) + h * DH + d];
    }
    for (int i = tid; i < KT * DH; i += 256) {
        int r = i / DH, d = i % DH;
        int kj = k0 + r;
        float kv = 0.f, vv = 0.f;
        if (kj >= 0) {
            const float* rowp = base + (size_t)kj * (3 * D_MODEL);
            kv = rowp[D_MODEL     + h * DH + d];
            vv = rowp[2 * D_MODEL + h * DH + d];
        }
        ks[r * SPAD + d] = kv;
        vs[r * SPAD + d] = vv;
    }
    __syncthreads();

    float sc[4][12];
    #pragma unroll
    for (int i = 0; i < 4; i++)
        #pragma unroll
        for (int jj = 0; jj < 12; jj++) sc[i][jj] = 0.f;

    for (int d = 0; d < DH; d++) {
        float a[4], bb[12];
        #pragma unroll
        for (int i = 0; i < 4; i++) a[i] = qs[(ty * 4 + i) * SPAD + d];
        #pragma unroll
        for (int jj = 0; jj < 12; jj++) bb[jj] = ks[(tx * 12 + jj) * SPAD + d];
        #pragma unroll
        for (int i = 0; i < 4; i++)
            #pragma unroll
            for (int jj = 0; jj < 12; jj++)
                sc[i][jj] += a[i] * bb[jj];
    }

    float invsum[4];
    #pragma unroll
    for (int i = 0; i < 4; i++) {
        int q = ty * 4 + i;
        float mx = -3.4e38f;
        #pragma unroll
        for (int jj = 0; jj < 12; jj++) {
            int j = tx * 12 + jj;
            bool ok = (j > q) && (j <= q + WINDOW) && (k0 + j >= 0);
            float sv = ok ? sc[i][jj] * 0.125f : -3.4e38f;
            sc[i][jj] = sv;
            mx = fmaxf(mx, sv);
        }
        #pragma unroll
        for (int o = 1; o < 16; o <<= 1)
            mx = fmaxf(mx, __shfl_xor_sync(0xffffffffu, mx, o));
        float su = 0.f;
        #pragma unroll
        for (int jj = 0; jj < 12; jj++) {
            float p = (sc[i][jj] > -1e37f) ? __expf(sc[i][jj] - mx) : 0.f;
            sc[i][jj] = p;
            su += p;
        }
        #pragma unroll
        for (int o = 1; o < 16; o <<= 1)
            su += __shfl_xor_sync(0xffffffffu, su, o);
        invsum[i] = 1.0f / su;
    }

    __syncthreads();
    #pragma unroll
    for (int i = 0; i < 4; i++)
        #pragma unroll
        for (int jj = 0; jj < 12; jj++)
            ss[(ty * 4 + i) * SSP + tx * 12 + jj] = sc[i][jj] * invsum[i];
    __syncthreads();

    float o[4][4];
    #pragma unroll
    for (int i = 0; i < 4; i++)
        #pragma unroll
        for (int l = 0; l < 4; l++) o[i][l] = 0.f;

    for (int j = 0; j < KT; j++) {
        float a[4], bv[4];
        #pragma unroll
        for (int i = 0; i < 4; i++) a[i] = ss[(ty * 4 + i) * SSP + j];
        #pragma unroll
        for (int l = 0; l < 4; l++) bv[l] = vs[j * SPAD + tx * 4 + l];
        #pragma unroll
        for (int i = 0; i < 4; i++)
            #pragma unroll
            for (int l = 0; l < 4; l++)
                o[i][l] += a[i] * bv[l];
    }
    #pragma unroll
    for (int i = 0; i < 4; i++) {
        size_t ro = (size_t)(b * SEQ + q0 + ty * 4 + i) * D_MODEL + h * DH + tx * 4;
        float h0 = __bfloat162float(__float2bfloat16_rn(o[i][0]));
        float h1 = __bfloat162float(__float2bfloat16_rn(o[i][1]));
        float h2 = __bfloat162float(__float2bfloat16_rn(o[i][2]));
        float h3 = __bfloat162float(__float2bfloat16_rn(o[i][3]));
        *(uint32_t*)&ch[ro]     = pack_bf2(o[i][0], o[i][1]);
        *(uint32_t*)&ch[ro + 2] = pack_bf2(o[i][2], o[i][3]);
        *(uint32_t*)&cl[ro]     = pack_bf2(o[i][0] - h0, o[i][1] - h1);
        *(uint32_t*)&cl[ro + 2] = pack_bf2(o[i][2] - h2, o[i][3] - h3);
    }
}

// ---------------- launcher ----------------
extern "C" void kernel_launch(void* const* d_in, const int* in_sizes, int n_in,
                              void* d_out, int out_size) {
    const float* x     = (const float*)d_in[0];
    const float* w_qkv = (const float*)d_in[1];
    const float* b_qkv = (const float*)d_in[2];
    const float* w_out = (const float*)d_in[3];
    const float* b_out = (const float*)d_in[4];
    const float* w_ff1 = (const float*)d_in[5];
    const float* b_ff1 = (const float*)d_in[6];
    const float* w_ff2 = (const float*)d_in[7];
    const float* b_ff2 = (const float*)d_in[8];
    const float* ln1_g = (const float*)d_in[9];
    const float* ln1_b = (const float*)d_in[10];
    const float* ln2_g = (const float*)d_in[11];
    const float* ln2_b = (const float*)d_in[12];
    float* out = (float*)d_out;

    float *qkv, *x2;
    __nv_bfloat16 *hh, *hl, *ch, *cl, *ffh, *ffl, *wh, *wl;
    cudaGetSymbolAddress((void**)&qkv, g_qkv);
    cudaGetSymbolAddress((void**)&x2,  g_x2);
    cudaGetSymbolAddress((void**)&hh,  g_hh);
    cudaGetSymbolAddress((void**)&hl,  g_hl);
    cudaGetSymbolAddress((void**)&ch,  g_ch);
    cudaGetSymbolAddress((void**)&cl,  g_cl);
    cudaGetSymbolAddress((void**)&ffh, g_ffh);
    cudaGetSymbolAddress((void**)&ffl, g_ffl);
    cudaGetSymbolAddress((void**)&wh,  g_wh);
    cudaGetSymbolAddress((void**)&wl,  g_wl);

    __nv_bfloat16 *wh_qkv = wh,           *wl_qkv = wl;
    __nv_bfloat16 *wh_out = wh + 3145728, *wl_out = wl + 3145728;
    __nv_bfloat16 *wh_ff1 = wh + 4194304, *wl_ff1 = wl + 4194304;
    __nv_bfloat16 *wh_ff2 = wh + 7340032, *wl_ff2 = wl + 7340032;

    cudaFuncSetAttribute(gemm_mma<0>, cudaFuncAttributeMaxDynamicSharedMemorySize, GEMM_SMEM);
    cudaFuncSetAttribute(gemm_mma<1>, cudaFuncAttributeMaxDynamicSharedMemorySize, GEMM_SMEM);
    cudaFuncSetAttribute(gemm_mma<2>, cudaFuncAttributeMaxDynamicSharedMemorySize, GEMM_SMEM);

    // 0. weight prep
    prep_w<<<dim3(3 * D_MODEL / 32, D_MODEL / 32), 256>>>(w_qkv, wh_qkv, wl_qkv, D_MODEL, 3 * D_MODEL);
    prep_w<<<dim3(D_MODEL / 32, D_MODEL / 32), 256>>>(w_out, wh_out, wl_out, D_MODEL, D_MODEL);
    prep_w<<<dim3(D_FF / 32, D_MODEL / 32), 256>>>(w_ff1, wh_ff1, wl_ff1, D_MODEL, D_FF);
    prep_w<<<dim3(D_MODEL / 32, D_FF / 32), 256>>>(w_ff2, wh_ff2, wl_ff2, D_FF, D_MODEL);

    // 1. LN1 -> split
    ln_split<<<ROWS, 256>>>(x, ln1_g, ln1_b, hh, hl);

    // 2. QKV projection
    gemm_mma<0><<<dim3(3 * D_MODEL / 128, ROWS / 128), 256, GEMM_SMEM>>>(
        hh, hl, wh_qkv, wl_qkv, b_qkv, nullptr, qkv, nullptr, nullptr,
        ROWS, 3 * D_MODEL, D_MODEL);

    // 3. attention -> split ctx
    size_t smem = (size_t)(QT * SPAD + 2 * KT * SPAD) * sizeof(float);
    cudaFuncSetAttribute(attn_kernel, cudaFuncAttributeMaxDynamicSharedMemorySize, (int)smem);
    attn_kernel<<<dim3(SEQ / QT, NH, BATCH), 256, smem>>>(qkv, ch, cl);

    // 4. out-projection + residual
    gemm_mma<1><<<dim3(D_MODEL / 128, ROWS / 128), 256, GEMM_SMEM>>>(
        ch, cl, wh_out, wl_out, b_out, x, x2, nullptr, nullptr,
        ROWS, D_MODEL, D_MODEL);

    // 5. LN2 -> split
    ln_split<<<ROWS, 256>>>(x2, ln2_g, ln2_b, hh, hl);

    // 6. FF1 + gelu -> split
    gemm_mma<2><<<dim3(D_FF / 128, ROWS / 128), 256, GEMM_SMEM>>>(
        hh, hl, wh_ff1, wl_ff1, b_ff1, nullptr, nullptr, ffh, ffl,
        ROWS, D_FF, D_MODEL);

    // 7. FF2 + residual -> output
    gemm_mma<1><<<dim3(D_MODEL / 128, ROWS / 128), 256, GEMM_SMEM>>>(
        ffh, ffl, wh_ff2, wl_ff2, b_ff2, x2, out, nullptr, nullptr,
        ROWS, D_MODEL, D_FF);
}

// round 10
// speedup vs baseline: 3.0213x; 2.1060x over previous
#include <cuda_runtime.h>
#include <cuda_fp16.h>
#include <math.h>
#include <stdint.h>

#define D_MODEL 1024
#define D_FF    3072
#define NH      16
#define DH      64
#define SEQ     2048
#define BATCH   2
#define ROWS    (BATCH*SEQ)   // 4096
#define WINDOW  128

// ---------------- scratch ----------------
__device__ float g_qkv[ROWS * 3 * D_MODEL];
__device__ float g_x2 [ROWS * D_MODEL];
__device__ __half g_h  [ROWS * D_MODEL];   // LN out fp16
__device__ __half g_ctx[ROWS * D_MODEL];   // attention ctx fp16
__device__ __half g_ff [ROWS * D_FF];      // gelu(ff1) fp16

// transposed fp16 weights: [N][K] layout
#define WT_TOTAL 10485760
__device__ __half g_w[WT_TOTAL];

// ---------------- PTX helpers ----------------
__device__ __forceinline__ uint32_t smem_u32(const void* p) {
    uint32_t a;
    asm("{ .reg .u64 t; cvta.to.shared.u64 t, %1; cvt.u32.u64 %0, t; }" : "=r"(a) : "l"(p));
    return a;
}
#define CP16(dst, src) \
    asm volatile("cp.async.cg.shared.global [%0], [%1], 16;" :: "r"(dst), "l"(src) : "memory")
#define CP_COMMIT() asm volatile("cp.async.commit_group;" ::: "memory")
#define CP_WAIT2()  asm volatile("cp.async.wait_group 2;" ::: "memory")

#define LDSM4(R, a) \
    asm volatile("ldmatrix.sync.aligned.m8n8.x4.shared.b16 {%0,%1,%2,%3}, [%4];" \
        : "=r"((R)[0]), "=r"((R)[1]), "=r"((R)[2]), "=r"((R)[3]) : "r"(a))

#define MMA_F16(d, a, b) \
    asm volatile("mma.sync.aligned.m16n8k16.row.col.f32.f16.f16.f32 " \
        "{%0,%1,%2,%3}, {%4,%5,%6,%7}, {%8,%9}, {%0,%1,%2,%3};" \
        : "+f"((d)[0]), "+f"((d)[1]), "+f"((d)[2]), "+f"((d)[3]) \
        : "r"((a)[0]), "r"((a)[1]), "r"((a)[2]), "r"((a)[3]), \
          "r"((b)[0]), "r"((b)[1]))

__device__ __forceinline__ float gelu_exact(float v) {
    return 0.5f * v * (1.0f + erff(v * 0.70710678118654752f));
}

// ---------------- weight prep: W[K][N] fp32 -> Wt[N][K] fp16 ----------------
__global__ void prep_w(const float* __restrict__ W, __half* __restrict__ Wt,
                       int K, int N) {
    __shared__ float t[32][33];
    int k0 = blockIdx.y * 32, n0 = blockIdx.x * 32;
    int tid = threadIdx.x;
    #pragma unroll
    for (int i = 0; i < 4; i++) {
        int lin = tid + 256 * i;
        int r = lin >> 5, c = lin & 31;
        t[r][c] = W[(size_t)(k0 + r) * N + n0 + c];
    }
    __syncthreads();
    #pragma unroll
    for (int i = 0; i < 4; i++) {
        int lin = tid + 256 * i;
        int n = lin >> 5, k = lin & 31;
        Wt[(size_t)(n0 + n) * K + k0 + k] = __float2half_rn(t[k][n]);
    }
}

// ---------------- LayerNorm -> fp16 ----------------
__global__ void ln_half(const float* __restrict__ x, const float* __restrict__ g,
                        const float* __restrict__ bb, __half* __restrict__ oh) {
    int row = blockIdx.x;
    const float* xr = x + (size_t)row * D_MODEL;
    int tid = threadIdx.x;
    float4 v = ((const float4*)xr)[tid];
    float s  = v.x + v.y + v.z + v.w;
    float s2 = v.x*v.x + v.y*v.y + v.z*v.z + v.w*v.w;
    __shared__ float rs[8], rs2[8];
    #pragma unroll
    for (int o = 16; o > 0; o >>= 1) {
        s  += __shfl_xor_sync(0xffffffffu, s,  o);
        s2 += __shfl_xor_sync(0xffffffffu, s2, o);
    }
    int w = tid >> 5, l = tid & 31;
    if (l == 0) { rs[w] = s; rs2[w] = s2; }
    __syncthreads();
    float ts = 0.f, ts2 = 0.f;
    #pragma unroll
    for (int i = 0; i < 8; i++) { ts += rs[i]; ts2 += rs2[i]; }
    float mu  = ts * (1.0f / D_MODEL);
    float var = ts2 * (1.0f / D_MODEL) - mu * mu;
    float inv = rsqrtf(var + 1e-5f);
    float4 gg = ((const float4*)g)[tid];
    float4 bv = ((const float4*)bb)[tid];
    float o0 = (v.x - mu) * inv * gg.x + bv.x;
    float o1 = (v.y - mu) * inv * gg.y + bv.y;
    float o2 = (v.z - mu) * inv * gg.z + bv.z;
    float o3 = (v.w - mu) * inv * gg.w + bv.w;
    size_t base = (size_t)row * D_MODEL + tid * 4;
    *(__half2*)&oh[base]     = __floats2half2_rn(o0, o1);
    *(__half2*)&oh[base + 2] = __floats2half2_rn(o2, o3);
}

// ---------------- fp16 pipelined mma GEMM ----------------
// C(M,N) = A(M,K) @ B(K,N):  A fp16 [M][K], B fp16 [N][K]. fp32 accum.
// CTA 128x128, BK=32, 8 warps (4m x 2n), warp tile 32x64.
// 4-stage cp.async; ldmatrix fragments.
// Stage layout (bytes): A 0 (10240), B 10240; stride 20480. 2 CTAs/SM.

#define ST_STRIDE 20480u
#define GEMM_SMEM (4 * 20480)

template<int EPI>  // 0: Cf=acc+bias  1: +res  2: Ch=half(gelu(acc+bias))
__global__ void __launch_bounds__(256, 2) gemm_mma(
    const __half* __restrict__ A, const __half* __restrict__ B,
    const float* __restrict__ bias, const float* __restrict__ res,
    float* __restrict__ Cf, __half* __restrict__ Ch,
    int M, int N, int K)
{
    extern __shared__ __align__(16) __half smg[];
    uint32_t sbase = smem_u32(smg);
    int tid = threadIdx.x, wid = tid >> 5, lane = tid & 31;
    int g = lane >> 2, tg = lane & 3;
    int wm = wid >> 1, wn = wid & 1;
    int bm = blockIdx.y * 128, bn = blockIdx.x * 128;
    int ns = K >> 5;

    // ldmatrix lane address components
    int lt = lane >> 3;
    int arow_l = (lt & 1) * 8 + (lane & 7);
    int ak_l   = (lt >> 1) * 8;
    int brow_l = (lt >> 1) * 8 + (lane & 7);
    int bk_l   = (lt & 1) * 8;

    // cp.async mapping: 128 rows x 4 chunks(16B) per tile, 2 chunks/thread/tile
    int lrow = tid >> 1, lkc = (tid & 1) * 2;
    const __half* gA = A + (size_t)(bm + lrow) * K + lkc * 8;
    const __half* gB = B + (size_t)(bn + lrow) * K + lkc * 8;
    uint32_t sA = (uint32_t)(lrow * 80 + lkc * 16);

    float acc[2][8][4];
    #pragma unroll
    for (int mi = 0; mi < 2; mi++)
        #pragma unroll
        for (int ni = 0; ni < 8; ni++)
            #pragma unroll
            for (int q = 0; q < 4; q++) acc[mi][ni][q] = 0.f;

    // ---- prologue: stages 0..2 ----
    #pragma unroll
    for (int p = 0; p < 3; p++) {
        uint32_t so = sbase + (uint32_t)p * ST_STRIDE;
        int k0 = p << 5;
        #pragma unroll
        for (int c = 0; c < 2; c++) {
            CP16(so + sA + c * 16u,          gA + k0 + c * 8);
            CP16(so + 10240u + sA + c * 16u, gB + k0 + c * 8);
        }
        CP_COMMIT();
    }

    for (int s = 0; s < ns; s++) {
        CP_WAIT2();
        __syncthreads();

        uint32_t st = sbase + (uint32_t)(s & 3) * ST_STRIDE;
        #pragma unroll
        for (int ks = 0; ks < 2; ks++) {
            int ks16 = ks * 16;
            uint32_t ah[2][4], bh[8][2];
            #pragma unroll
            for (int mi = 0; mi < 2; mi++) {
                uint32_t ao = st + (uint32_t)((wm * 32 + mi * 16 + arow_l) * 40 + ks16 + ak_l) * 2;
                LDSM4(ah[mi], ao);
            }
            #pragma unroll
            for (int nb = 0; nb < 4; nb++) {
                uint32_t bo = st + 10240u +
                    (uint32_t)((wn * 64 + nb * 16 + brow_l) * 40 + ks16 + bk_l) * 2;
                uint32_t r[4];
                LDSM4(r, bo);
                bh[2*nb][0] = r[0]; bh[2*nb][1] = r[1];
                bh[2*nb+1][0] = r[2]; bh[2*nb+1][1] = r[3];
            }
            #pragma unroll
            for (int mi = 0; mi < 2; mi++)
                #pragma unroll
                for (int ni = 0; ni < 8; ni++)
                    MMA_F16(acc[mi][ni], ah[mi], bh[ni]);
        }

        // refill slot (s+3)&3
        if (s + 3 < ns) {
            uint32_t so = sbase + (uint32_t)((s + 3) & 3) * ST_STRIDE;
            int k0 = (s + 3) << 5;
            #pragma unroll
            for (int c = 0; c < 2; c++) {
                CP16(so + sA + c * 16u,          gA + k0 + c * 8);
                CP16(so + 10240u + sA + c * 16u, gB + k0 + c * 8);
            }
        }
        CP_COMMIT();
    }

    // ---- epilogue ----
    #pragma unroll
    for (int mi = 0; mi < 2; mi++) {
        int r0 = bm + wm * 32 + mi * 16 + g;
        int r1 = r0 + 8;
        #pragma unroll
        for (int ni = 0; ni < 8; ni++) {
            int cn = bn + wn * 64 + ni * 8 + tg * 2;
            float2 bv = *(const float2*)&bias[cn];
            float x0 = acc[mi][ni][0] + bv.x;
            float x1 = acc[mi][ni][1] + bv.y;
            float x2 = acc[mi][ni][2] + bv.x;
            float x3 = acc[mi][ni][3] + bv.y;
            size_t o0 = (size_t)r0 * N + cn;
            size_t o1 = (size_t)r1 * N + cn;
            if (EPI == 1) {
                float2 q0 = *(const float2*)&res[o0];
                float2 q1 = *(const float2*)&res[o1];
                x0 += q0.x; x1 += q0.y; x2 += q1.x; x3 += q1.y;
            }
            if (EPI == 2) {
                x0 = gelu_exact(x0); x1 = gelu_exact(x1);
                x2 = gelu_exact(x2); x3 = gelu_exact(x3);
                *(__half2*)&Ch[o0] = __floats2half2_rn(x0, x1);
                *(__half2*)&Ch[o1] = __floats2half2_rn(x2, x3);
            } else {
                float2 s0 = {x0, x1}, s1 = {x2, x3};
                *(float2*)&Cf[o0] = s0;
                *(float2*)&Cf[o1] = s1;
            }
        }
    }
}

// ---------------- sliding-window attention (verified; writes fp16 ctx) ----------------
#define QT   64
#define KT   192
#define SPAD 65
#define SSP  196

__global__ void attn_kernel(const float* __restrict__ qkv, __half* __restrict__ ctx) {
    extern __shared__ float smf[];
    float* qs = smf;
    float* ks = smf + QT * SPAD;
    float* vs = ks + KT * SPAD;
    float* ss = smf;

    int tid = threadIdx.x;
    int tx = tid & 15, ty = tid >> 4;
    int q0 = blockIdx.x * QT;
    int h  = blockIdx.y;
    int b  = blockIdx.z;
    int k0 = q0 - WINDOW;
    const float* base = qkv + (size_t)b * SEQ * (3 * D_MODEL);

    for (int i = tid; i < QT * DH; i += 256) {
        int r = i / DH, d = i % DH;
        qs[r * SPAD + d] = base[(size_t)(q0 + r) * (3 * D_MODEL) + h * DH + d];
    }
    for (int i = tid; i < KT * DH; i += 256) {
        int r = i / DH, d = i % DH;
        int kj = k0 + r;
        float kv = 0.f, vv = 0.f;
        if (kj >= 0) {
            const float* rowp = base + (size_t)kj * (3 * D_MODEL);
            kv = rowp[D_MODEL     + h * DH + d];
            vv = rowp[2 * D_MODEL + h * DH + d];
        }
        ks[r * SPAD + d] = kv;
        vs[r * SPAD + d] = vv;
    }
    __syncthreads();

    float sc[4][12];
    #pragma unroll
    for (int i = 0; i < 4; i++)
        #pragma unroll
        for (int jj = 0; jj < 12; jj++) sc[i][jj] = 0.f;

    for (int d = 0; d < DH; d++) {
        float a[4], bb[12];
        #pragma unroll
        for (int i = 0; i < 4; i++) a[i] = qs[(ty * 4 + i) * SPAD + d];
        #pragma unroll
        for (int jj = 0; jj < 12; jj++) bb[jj] = ks[(tx * 12 + jj) * SPAD + d];
        #pragma unroll
        for (int i = 0; i < 4; i++)
            #pragma unroll
            for (int jj = 0; jj < 12; jj++)
                sc[i][jj] += a[i] * bb[jj];
    }

    float invsum[4];
    #pragma unroll
    for (int i = 0; i < 4; i++) {
        int q = ty * 4 + i;
        float mx = -3.4e38f;
        #pragma unroll
        for (int jj = 0; jj < 12; jj++) {
            int j = tx * 12 + jj;
            bool ok = (j > q) && (j <= q + WINDOW) && (k0 + j >= 0);
            float sv = ok ? sc[i][jj] * 0.125f : -3.4e38f;
            sc[i][jj] = sv;
            mx = fmaxf(mx, sv);
        }
        #pragma unroll
        for (int o = 1; o < 16; o <<= 1)
            mx = fmaxf(mx, __shfl_xor_sync(0xffffffffu, mx, o));
        float su = 0.f;
        #pragma unroll
        for (int jj = 0; jj < 12; jj++) {
            float p = (sc[i][jj] > -1e37f) ? __expf(sc[i][jj] - mx) : 0.f;
            sc[i][jj] = p;
            su += p;
        }
        #pragma unroll
        for (int o = 1; o < 16; o <<= 1)
            su += __shfl_xor_sync(0xffffffffu, su, o);
        invsum[i] = 1.0f / su;
    }

    __syncthreads();
    #pragma unroll
    for (int i = 0; i < 4; i++)
        #pragma unroll
        for (int jj = 0; jj < 12; jj++)
            ss[(ty * 4 + i) * SSP + tx * 12 + jj] = sc[i][jj] * invsum[i];
    __syncthreads();

    float o[4][4];
    #pragma unroll
    for (int i = 0; i < 4; i++)
        #pragma unroll
        for (int l = 0; l < 4; l++) o[i][l] = 0.f;

    for (int j = 0; j < KT; j++) {
        float a[4], bv[4];
        #pragma unroll
        for (int i = 0; i < 4; i++) a[i] = ss[(ty * 4 + i) * SSP + j];
        #pragma unroll
        for (int l = 0; l < 4; l++) bv[l] = vs[j * SPAD + tx * 4 + l];
        #pragma unroll
        for (int i = 0; i < 4; i++)
            #pragma unroll
            for (int l = 0; l < 4; l++)
                o[i][l] += a[i] * bv[l];
    }
    #pragma unroll
    for (int i = 0; i < 4; i++) {
        size_t ro = (size_t)(b * SEQ + q0 + ty * 4 + i) * D_MODEL + h * DH + tx * 4;
        *(__half2*)&ctx[ro]     = __floats2half2_rn(o[i][0], o[i][1]);
        *(__half2*)&ctx[ro + 2] = __floats2half2_rn(o[i][2], o[i][3]);
    }
}

// ---------------- launcher ----------------
extern "C" void kernel_launch(void* const* d_in, const int* in_sizes, int n_in,
                              void* d_out, int out_size) {
    const float* x     = (const float*)d_in[0];
    const float* w_qkv = (const float*)d_in[1];
    const float* b_qkv = (const float*)d_in[2];
    const float* w_out = (const float*)d_in[3];
    const float* b_out = (const float*)d_in[4];
    const float* w_ff1 = (const float*)d_in[5];
    const float* b_ff1 = (const float*)d_in[6];
    const float* w_ff2 = (const float*)d_in[7];
    const float* b_ff2 = (const float*)d_in[8];
    const float* ln1_g = (const float*)d_in[9];
    const float* ln1_b = (const float*)d_in[10];
    const float* ln2_g = (const float*)d_in[11];
    const float* ln2_b = (const float*)d_in[12];
    float* out = (float*)d_out;

    float *qkv, *x2;
    __half *h, *ctx, *ff, *w;
    cudaGetSymbolAddress((void**)&qkv, g_qkv);
    cudaGetSymbolAddress((void**)&x2,  g_x2);
    cudaGetSymbolAddress((void**)&h,   g_h);
    cudaGetSymbolAddress((void**)&ctx, g_ctx);
    cudaGetSymbolAddress((void**)&ff,  g_ff);
    cudaGetSymbolAddress((void**)&w,   g_w);

    __half *w_qkv_t = w;
    __half *w_out_t = w + 3145728;
    __half *w_ff1_t = w + 4194304;
    __half *w_ff2_t = w + 7340032;

    cudaFuncSetAttribute(gemm_mma<0>, cudaFuncAttributeMaxDynamicSharedMemorySize, GEMM_SMEM);
    cudaFuncSetAttribute(gemm_mma<1>, cudaFuncAttributeMaxDynamicSharedMemorySize, GEMM_SMEM);
    cudaFuncSetAttribute(gemm_mma<2>, cudaFuncAttributeMaxDynamicSharedMemorySize, GEMM_SMEM);

    // 0. weight prep (transpose + fp16)
    prep_w<<<dim3(3 * D_MODEL / 32, D_MODEL / 32), 256>>>(w_qkv, w_qkv_t, D_MODEL, 3 * D_MODEL);
    prep_w<<<dim3(D_MODEL / 32, D_MODEL / 32), 256>>>(w_out, w_out_t, D_MODEL, D_MODEL);
    prep_w<<<dim3(D_FF / 32, D_MODEL / 32), 256>>>(w_ff1, w_ff1_t, D_MODEL, D_FF);
    prep_w<<<dim3(D_MODEL / 32, D_FF / 32), 256>>>(w_ff2, w_ff2_t, D_FF, D_MODEL);

    // 1. LN1 -> fp16
    ln_half<<<ROWS, 256>>>(x, ln1_g, ln1_b, h);

    // 2. QKV projection
    gemm_mma<0><<<dim3(3 * D_MODEL / 128, ROWS / 128), 256, GEMM_SMEM>>>(
        h, w_qkv_t, b_qkv, nullptr, qkv, nullptr, ROWS, 3 * D_MODEL, D_MODEL);

    // 3. attention -> fp16 ctx
    size_t smem = (size_t)(QT * SPAD + 2 * KT * SPAD) * sizeof(float);
    cudaFuncSetAttribute(attn_kernel, cudaFuncAttributeMaxDynamicSharedMemorySize, (int)smem);
    attn_kernel<<<dim3(SEQ / QT, NH, BATCH), 256, smem>>>(qkv, ctx);

    // 4. out-projection + residual
    gemm_mma<1><<<dim3(D_MODEL / 128, ROWS / 128), 256, GEMM_SMEM>>>(
        ctx, w_out_t, b_out, x, x2, nullptr, ROWS, D_MODEL, D_MODEL);

    // 5. LN2 -> fp16
    ln_half<<<ROWS, 256>>>(x2, ln2_g, ln2_b, h);

    // 6. FF1 + gelu -> fp16
    gemm_mma<2><<<dim3(D_FF / 128, ROWS / 128), 256, GEMM_SMEM>>>(
        h, w_ff1_t, b_ff1, nullptr, nullptr, ff, ROWS, D_FF, D_MODEL);

    // 7. FF2 + residual -> output
    gemm_mma<1><<<dim3(D_MODEL / 128, ROWS / 128), 256, GEMM_SMEM>>>(
        ff, w_ff2_t, b_ff2, x2, out, nullptr, ROWS, D_MODEL, D_FF);
}

// round 13
// speedup vs baseline: 4.1733x; 1.3813x over previous
#include <cuda_runtime.h>
#include <cuda_fp16.h>
#include <math.h>
#include <stdint.h>

#define D_MODEL 1024
#define D_FF    3072
#define NH      16
#define DH      64
#define SEQ     2048
#define BATCH   2
#define ROWS    (BATCH*SEQ)   // 4096
#define WINDOW  128

// ---------------- scratch ----------------
__device__ float  g_x2 [ROWS * D_MODEL];
__device__ __half g_qkvh[ROWS * 3 * D_MODEL]; // QKV proj fp16
__device__ __half g_h  [ROWS * D_MODEL];      // LN out fp16
__device__ __half g_ctx[ROWS * D_MODEL];      // attention ctx fp16
__device__ __half g_ff [ROWS * D_FF];         // gelu(ff1) fp16

// transposed fp16 weights: [N][K] layout
#define WT_TOTAL 10485760
__device__ __half g_w[WT_TOTAL];

// ---------------- PTX helpers ----------------
__device__ __forceinline__ uint32_t smem_u32(const void* p) {
    uint32_t a;
    asm("{ .reg .u64 t; cvta.to.shared.u64 t, %1; cvt.u32.u64 %0, t; }" : "=r"(a) : "l"(p));
    return a;
}
#define CP16(dst, src) \
    asm volatile("cp.async.cg.shared.global [%0], [%1], 16;" :: "r"(dst), "l"(src) : "memory")
#define CP_COMMIT() asm volatile("cp.async.commit_group;" ::: "memory")
#define CP_WAIT2()  asm volatile("cp.async.wait_group 2;" ::: "memory")

#define LDSM4(R, a) \
    asm volatile("ldmatrix.sync.aligned.m8n8.x4.shared.b16 {%0,%1,%2,%3}, [%4];" \
        : "=r"((R)[0]), "=r"((R)[1]), "=r"((R)[2]), "=r"((R)[3]) : "r"(a))
#define LDSM4T(R, a) \
    asm volatile("ldmatrix.sync.aligned.m8n8.x4.trans.shared.b16 {%0,%1,%2,%3}, [%4];" \
        : "=r"((R)[0]), "=r"((R)[1]), "=r"((R)[2]), "=r"((R)[3]) : "r"(a))

#define MMA_F16(d, a, b) \
    asm volatile("mma.sync.aligned.m16n8k16.row.col.f32.f16.f16.f32 " \
        "{%0,%1,%2,%3}, {%4,%5,%6,%7}, {%8,%9}, {%0,%1,%2,%3};" \
        : "+f"((d)[0]), "+f"((d)[1]), "+f"((d)[2]), "+f"((d)[3]) \
        : "r"((a)[0]), "r"((a)[1]), "r"((a)[2]), "r"((a)[3]), \
          "r"((b)[0]), "r"((b)[1]))

__device__ __forceinline__ float gelu_exact(float v) {
    return 0.5f * v * (1.0f + erff(v * 0.70710678118654752f));
}

// ---------------- weight prep: W[K][N] fp32 -> Wt[N][K] fp16 ----------------
__global__ void prep_w(const float* __restrict__ W, __half* __restrict__ Wt,
                       int K, int N) {
    __shared__ float t[32][33];
    int k0 = blockIdx.y * 32, n0 = blockIdx.x * 32;
    int tid = threadIdx.x;
    #pragma unroll
    for (int i = 0; i < 4; i++) {
        int lin = tid + 256 * i;
        int r = lin >> 5, c = lin & 31;
        t[r][c] = W[(size_t)(k0 + r) * N + n0 + c];
    }
    __syncthreads();
    #pragma unroll
    for (int i = 0; i < 4; i++) {
        int lin = tid + 256 * i;
        int n = lin >> 5, k = lin & 31;
        Wt[(size_t)(n0 + n) * K + k0 + k] = __float2half_rn(t[k][n]);
    }
}

// ---------------- LayerNorm -> fp16 ----------------
__global__ void ln_half(const float* __restrict__ x, const float* __restrict__ g,
                        const float* __restrict__ bb, __half* __restrict__ oh) {
    int row = blockIdx.x;
    const float* xr = x + (size_t)row * D_MODEL;
    int tid = threadIdx.x;
    float4 v = ((const float4*)xr)[tid];
    float s  = v.x + v.y + v.z + v.w;
    float s2 = v.x*v.x + v.y*v.y + v.z*v.z + v.w*v.w;
    __shared__ float rs[8], rs2[8];
    #pragma unroll
    for (int o = 16; o > 0; o >>= 1) {
        s  += __shfl_xor_sync(0xffffffffu, s,  o);
        s2 += __shfl_xor_sync(0xffffffffu, s2, o);
    }
    int w = tid >> 5, l = tid & 31;
    if (l == 0) { rs[w] = s; rs2[w] = s2; }
    __syncthreads();
    float ts = 0.f, ts2 = 0.f;
    #pragma unroll
    for (int i = 0; i < 8; i++) { ts += rs[i]; ts2 += rs2[i]; }
    float mu  = ts * (1.0f / D_MODEL);
    float var = ts2 * (1.0f / D_MODEL) - mu * mu;
    float inv = rsqrtf(var + 1e-5f);
    float4 gg = ((const float4*)g)[tid];
    float4 bv = ((const float4*)bb)[tid];
    float o0 = (v.x - mu) * inv * gg.x + bv.x;
    float o1 = (v.y - mu) * inv * gg.y + bv.y;
    float o2 = (v.z - mu) * inv * gg.z + bv.z;
    float o3 = (v.w - mu) * inv * gg.w + bv.w;
    size_t base = (size_t)row * D_MODEL + tid * 4;
    *(__half2*)&oh[base]     = __floats2half2_rn(o0, o1);
    *(__half2*)&oh[base + 2] = __floats2half2_rn(o2, o3);
}

// ---------------- fp16 pipelined mma GEMM (as R9) ----------------
#define ST_STRIDE 20480u
#define GEMM_SMEM (4 * 20480)

template<int EPI>  // 0: Cf=acc+bias  1: +res  2: Ch=half(gelu(acc+bias))  3: Ch=half(acc+bias)
__global__ void __launch_bounds__(256, 2) gemm_mma(
    const __half* __restrict__ A, const __half* __restrict__ B,
    const float* __restrict__ bias, const float* __restrict__ res,
    float* __restrict__ Cf, __half* __restrict__ Ch,
    int M, int N, int K)
{
    extern __shared__ __align__(16) __half smg[];
    uint32_t sbase = smem_u32(smg);
    int tid = threadIdx.x, wid = tid >> 5, lane = tid & 31;
    int g = lane >> 2, tg = lane & 3;
    int wm = wid >> 1, wn = wid & 1;
    int bm = blockIdx.y * 128, bn = blockIdx.x * 128;
    int ns = K >> 5;

    int lt = lane >> 3;
    int arow_l = (lt & 1) * 8 + (lane & 7);
    int ak_l   = (lt >> 1) * 8;
    int brow_l = (lt >> 1) * 8 + (lane & 7);
    int bk_l   = (lt & 1) * 8;

    int lrow = tid >> 1, lkc = (tid & 1) * 2;
    const __half* gA = A + (size_t)(bm + lrow) * K + lkc * 8;
    const __half* gB = B + (size_t)(bn + lrow) * K + lkc * 8;
    uint32_t sA = (uint32_t)(lrow * 80 + lkc * 16);

    float acc[2][8][4];
    #pragma unroll
    for (int mi = 0; mi < 2; mi++)
        #pragma unroll
        for (int ni = 0; ni < 8; ni++)
            #pragma unroll
            for (int q = 0; q < 4; q++) acc[mi][ni][q] = 0.f;

    #pragma unroll
    for (int p = 0; p < 3; p++) {
        uint32_t so = sbase + (uint32_t)p * ST_STRIDE;
        int k0 = p << 5;
        #pragma unroll
        for (int c = 0; c < 2; c++) {
            CP16(so + sA + c * 16u,          gA + k0 + c * 8);
            CP16(so + 10240u + sA + c * 16u, gB + k0 + c * 8);
        }
        CP_COMMIT();
    }

    for (int s = 0; s < ns; s++) {
        CP_WAIT2();
        __syncthreads();

        uint32_t st = sbase + (uint32_t)(s & 3) * ST_STRIDE;
        #pragma unroll
        for (int ks = 0; ks < 2; ks++) {
            int ks16 = ks * 16;
            uint32_t ah[2][4], bh[8][2];
            #pragma unroll
            for (int mi = 0; mi < 2; mi++) {
                uint32_t ao = st + (uint32_t)((wm * 32 + mi * 16 + arow_l) * 40 + ks16 + ak_l) * 2;
                LDSM4(ah[mi], ao);
            }
            #pragma unroll
            for (int nb = 0; nb < 4; nb++) {
                uint32_t bo = st + 10240u +
                    (uint32_t)((wn * 64 + nb * 16 + brow_l) * 40 + ks16 + bk_l) * 2;
                uint32_t r[4];
                LDSM4(r, bo);
                bh[2*nb][0] = r[0]; bh[2*nb][1] = r[1];
                bh[2*nb+1][0] = r[2]; bh[2*nb+1][1] = r[3];
            }
            #pragma unroll
            for (int mi = 0; mi < 2; mi++)
                #pragma unroll
                for (int ni = 0; ni < 8; ni++)
                    MMA_F16(acc[mi][ni], ah[mi], bh[ni]);
        }

        if (s + 3 < ns) {
            uint32_t so = sbase + (uint32_t)((s + 3) & 3) * ST_STRIDE;
            int k0 = (s + 3) << 5;
            #pragma unroll
            for (int c = 0; c < 2; c++) {
                CP16(so + sA + c * 16u,          gA + k0 + c * 8);
                CP16(so + 10240u + sA + c * 16u, gB + k0 + c * 8);
            }
        }
        CP_COMMIT();
    }

    #pragma unroll
    for (int mi = 0; mi < 2; mi++) {
        int r0 = bm + wm * 32 + mi * 16 + g;
        int r1 = r0 + 8;
        #pragma unroll
        for (int ni = 0; ni < 8; ni++) {
            int cn = bn + wn * 64 + ni * 8 + tg * 2;
            float2 bv = *(const float2*)&bias[cn];
            float x0 = acc[mi][ni][0] + bv.x;
            float x1 = acc[mi][ni][1] + bv.y;
            float x2 = acc[mi][ni][2] + bv.x;
            float x3 = acc[mi][ni][3] + bv.y;
            size_t o0 = (size_t)r0 * N + cn;
            size_t o1 = (size_t)r1 * N + cn;
            if (EPI == 1) {
                float2 q0 = *(const float2*)&res[o0];
                float2 q1 = *(const float2*)&res[o1];
                x0 += q0.x; x1 += q0.y; x2 += q1.x; x3 += q1.y;
            }
            if (EPI == 2) {
                x0 = gelu_exact(x0); x1 = gelu_exact(x1);
                x2 = gelu_exact(x2); x3 = gelu_exact(x3);
            }
            if (EPI == 2 || EPI == 3) {
                *(__half2*)&Ch[o0] = __floats2half2_rn(x0, x1);
                *(__half2*)&Ch[o1] = __floats2half2_rn(x2, x3);
            } else {
                float2 s0 = {x0, x1}, s1 = {x2, x3};
                *(float2*)&Cf[o0] = s0;
                *(float2*)&Cf[o1] = s1;
            }
        }
    }
}

// ---------------- tensor-core sliding-window attention ----------------
// Per block: 64 queries, 192-key band. 8 warps (wm 0..3 = 16-row tile, wn 0..1).
// S phase: warp (wm,wn) computes S[wm*16..+16][wn*96..+96] fp32, softmax with
// cross-wn combine via SMEM, P fp16 -> PS. PV phase: warp (wm,wn) computes
// O[wm*16..+16][wn*32..+32] over all 192 keys. V B-fragments via ldmatrix.trans.
// SMEM (halves): QS[64][72] @0, KS[192][72] @4608, VS[192][72] @18432,
//                PS[64][200] @32256.  Total 90112 B.
#define ATT_SMEM 90112

__global__ void __launch_bounds__(256, 2) attn_mma(const __half* __restrict__ qkv,
                                                   __half* __restrict__ ctx) {
    extern __shared__ __align__(16) __half asmem[];
    __shared__ float RM[2][4][16], RS[2][4][16];
    __half* QS = asmem;
    __half* KS = asmem + 4608;
    __half* VS = asmem + 18432;
    __half* PS = asmem + 32256;
    uint32_t qb = smem_u32(QS), kbs = smem_u32(KS), vbs = smem_u32(VS), pbs = smem_u32(PS);

    int tid = threadIdx.x, wid = tid >> 5, lane = tid & 31;
    int g = lane >> 2, tg = lane & 3;
    int wm = wid >> 1, wn = wid & 1;
    int lt = lane >> 3;
    int arow_l = (lt & 1) * 8 + (lane & 7);
    int ak_l   = (lt >> 1) * 8;
    int brow_l = (lt >> 1) * 8 + (lane & 7);
    int bk_l   = (lt & 1) * 8;

    int q0 = blockIdx.x * 64, h = blockIdx.y, b = blockIdx.z;
    int k0 = q0 - WINDOW;
    const __half* base = qkv + (size_t)b * SEQ * (3 * D_MODEL);

    // ---- load Q, K, V (fp16, vectorized) ----
    #pragma unroll
    for (int i = 0; i < 2; i++) {
        int idx = tid + 256 * i;
        int r = idx >> 3, c = idx & 7;
        uint4 v = *(const uint4*)(base + (size_t)(q0 + r) * (3 * D_MODEL) + h * DH + c * 8);
        *(uint4*)(QS + r * 72 + c * 8) = v;
    }
    #pragma unroll
    for (int i = 0; i < 6; i++) {
        int idx = tid + 256 * i;
        int r = idx >> 3, c = idx & 7;
        int kj = k0 + r;
        uint4 kv = {0,0,0,0}, vv = {0,0,0,0};
        if (kj >= 0) {
            kv = *(const uint4*)(base + (size_t)kj * (3 * D_MODEL) + D_MODEL + h * DH + c * 8);
            vv = *(const uint4*)(base + (size_t)kj * (3 * D_MODEL) + 2 * D_MODEL + h * DH + c * 8);
        }
        *(uint4*)(KS + r * 72 + c * 8) = kv;
        *(uint4*)(VS + r * 72 + c * 8) = vv;
    }
    __syncthreads();

    // ---- S = Q K^T ----
    uint32_t aq[4][4];
    #pragma unroll
    for (int ks = 0; ks < 4; ks++)
        LDSM4(aq[ks], qb + (uint32_t)((wm * 16 + arow_l) * 72 + ks * 16 + ak_l) * 2);

    float sacc[12][4];
    #pragma unroll
    for (int t = 0; t < 12; t++)
        #pragma unroll
        for (int q = 0; q < 4; q++) sacc[t][q] = 0.f;

    #pragma unroll
    for (int c = 0; c < 6; c++) {
        int kb2 = wn * 96 + c * 16;
        #pragma unroll
        for (int ks = 0; ks < 4; ks++) {
            uint32_t r[4];
            LDSM4(r, kbs + (uint32_t)((kb2 + brow_l) * 72 + ks * 16 + bk_l) * 2);
            uint32_t b0[2] = {r[0], r[1]}, b1[2] = {r[2], r[3]};
            MMA_F16(sacc[2*c],   aq[ks], b0);
            MMA_F16(sacc[2*c+1], aq[ks], b1);
        }
    }

    // ---- mask + scale + local rowmax ----
    int r0 = wm * 16 + g, r1 = r0 + 8;
    float m0 = -1e30f, m1 = -1e30f;
    #pragma unroll
    for (int t = 0; t < 12; t++) {
        int j0 = wn * 96 + t * 8 + tg * 2, j1 = j0 + 1;
        bool a00 = (j0 > r0) && (j0 <= r0 + WINDOW) && (k0 + j0 >= 0);
        bool a01 = (j1 > r0) && (j1 <= r0 + WINDOW) && (k0 + j1 >= 0);
        bool a10 = (j0 > r1) && (j0 <= r1 + WINDOW) && (k0 + j0 >= 0);
        bool a11 = (j1 > r1) && (j1 <= r1 + WINDOW) && (k0 + j1 >= 0);
        sacc[t][0] = a00 ? sacc[t][0] * 0.125f : -1e30f;
        sacc[t][1] = a01 ? sacc[t][1] * 0.125f : -1e30f;
        sacc[t][2] = a10 ? sacc[t][2] * 0.125f : -1e30f;
        sacc[t][3] = a11 ? sacc[t][3] * 0.125f : -1e30f;
        m0 = fmaxf(m0, fmaxf(sacc[t][0], sacc[t][1]));
        m1 = fmaxf(m1, fmaxf(sacc[t][2], sacc[t][3]));
    }
    m0 = fmaxf(m0, __shfl_xor_sync(0xffffffffu, m0, 1));
    m0 = fmaxf(m0, __shfl_xor_sync(0xffffffffu, m0, 2));
    m1 = fmaxf(m1, __shfl_xor_sync(0xffffffffu, m1, 1));
    m1 = fmaxf(m1, __shfl_xor_sync(0xffffffffu, m1, 2));
    if (tg == 0) { RM[wn][wm][g] = m0; RM[wn][wm][g + 8] = m1; }
    __syncthreads();
    float gm0 = fmaxf(RM[0][wm][g],     RM[1][wm][g]);
    float gm1 = fmaxf(RM[0][wm][g + 8], RM[1][wm][g + 8]);

    // ---- exp + local sums; P -> PS ----
    float s0 = 0.f, s1 = 0.f;
    #pragma unroll
    for (int t = 0; t < 12; t++) {
        float p0 = __expf(sacc[t][0] - gm0);
        float p1 = __expf(sacc[t][1] - gm0);
        float p2 = __expf(sacc[t][2] - gm1);
        float p3 = __expf(sacc[t][3] - gm1);
        s0 += p0 + p1; s1 += p2 + p3;
        int col = wn * 96 + t * 8 + tg * 2;
        *(__half2*)(PS + r0 * 200 + col) = __floats2half2_rn(p0, p1);
        *(__half2*)(PS + r1 * 200 + col) = __floats2half2_rn(p2, p3);
    }
    s0 += __shfl_xor_sync(0xffffffffu, s0, 1);
    s0 += __shfl_xor_sync(0xffffffffu, s0, 2);
    s1 += __shfl_xor_sync(0xffffffffu, s1, 1);
    s1 += __shfl_xor_sync(0xffffffffu, s1, 2);
    if (tg == 0) { RS[wn][wm][g] = s0; RS[wn][wm][g + 8] = s1; }
    __syncthreads();

    // ---- O = P V  (warp covers dh slice wn*32..+32, all 192 keys) ----
    float oacc[4][4];
    #pragma unroll
    for (int t = 0; t < 4; t++)
        #pragma unroll
        for (int q = 0; q < 4; q++) oacc[t][q] = 0.f;

    #pragma unroll
    for (int kc = 0; kc < 12; kc++) {
        uint32_t pa[4];
        LDSM4(pa, pbs + (uint32_t)((wm * 16 + arow_l) * 200 + kc * 16 + ak_l) * 2);
        #pragma unroll
        for (int nh2 = 0; nh2 < 2; nh2++) {
            uint32_t r[4];
            LDSM4T(r, vbs + (uint32_t)((kc * 16 + arow_l) * 72 + wn * 32 + nh2 * 16 + ak_l) * 2);
            uint32_t b0[2] = {r[0], r[1]}, b1[2] = {r[2], r[3]};
            MMA_F16(oacc[nh2*2],   pa, b0);
            MMA_F16(oacc[nh2*2+1], pa, b1);
        }
    }

    float inv0 = 1.f / (RS[0][wm][g]     + RS[1][wm][g]);
    float inv1 = 1.f / (RS[0][wm][g + 8] + RS[1][wm][g + 8]);
    size_t ro0 = (size_t)(b * SEQ + q0 + r0) * D_MODEL + h * DH;
    size_t ro1 = (size_t)(b * SEQ + q0 + r1) * D_MODEL + h * DH;
    #pragma unroll
    for (int t = 0; t < 4; t++) {
        int col = wn * 32 + t * 8 + tg * 2;
        *(__half2*)(ctx + ro0 + col) = __floats2half2_rn(oacc[t][0] * inv0, oacc[t][1] * inv0);
        *(__half2*)(ctx + ro1 + col) = __floats2half2_rn(oacc[t][2] * inv1, oacc[t][3] * inv1);
    }
}

// ---------------- launcher ----------------
extern "C" void kernel_launch(void* const* d_in, const int* in_sizes, int n_in,
                              void* d_out, int out_size) {
    const float* x     = (const float*)d_in[0];
    const float* w_qkv = (const float*)d_in[1];
    const float* b_qkv = (const float*)d_in[2];
    const float* w_out = (const float*)d_in[3];
    const float* b_out = (const float*)d_in[4];
    const float* w_ff1 = (const float*)d_in[5];
    const float* b_ff1 = (const float*)d_in[6];
    const float* w_ff2 = (const float*)d_in[7];
    const float* b_ff2 = (const float*)d_in[8];
    const float* ln1_g = (const float*)d_in[9];
    const float* ln1_b = (const float*)d_in[10];
    const float* ln2_g = (const float*)d_in[11];
    const float* ln2_b = (const float*)d_in[12];
    float* out = (float*)d_out;

    float *x2;
    __half *qkvh, *h, *ctx, *ff, *w;
    cudaGetSymbolAddress((void**)&x2,   g_x2);
    cudaGetSymbolAddress((void**)&qkvh, g_qkvh);
    cudaGetSymbolAddress((void**)&h,    g_h);
    cudaGetSymbolAddress((void**)&ctx,  g_ctx);
    cudaGetSymbolAddress((void**)&ff,   g_ff);
    cudaGetSymbolAddress((void**)&w,    g_w);

    __half *w_qkv_t = w;
    __half *w_out_t = w + 3145728;
    __half *w_ff1_t = w + 4194304;
    __half *w_ff2_t = w + 7340032;

    cudaFuncSetAttribute(gemm_mma<1>, cudaFuncAttributeMaxDynamicSharedMemorySize, GEMM_SMEM);
    cudaFuncSetAttribute(gemm_mma<2>, cudaFuncAttributeMaxDynamicSharedMemorySize, GEMM_SMEM);
    cudaFuncSetAttribute(gemm_mma<3>, cudaFuncAttributeMaxDynamicSharedMemorySize, GEMM_SMEM);
    cudaFuncSetAttribute(attn_mma, cudaFuncAttributeMaxDynamicSharedMemorySize, ATT_SMEM);

    // 0. weight prep (transpose + fp16)
    prep_w<<<dim3(3 * D_MODEL / 32, D_MODEL / 32), 256>>>(w_qkv, w_qkv_t, D_MODEL, 3 * D_MODEL);
    prep_w<<<dim3(D_MODEL / 32, D_MODEL / 32), 256>>>(w_out, w_out_t, D_MODEL, D_MODEL);
    prep_w<<<dim3(D_FF / 32, D_MODEL / 32), 256>>>(w_ff1, w_ff1_t, D_MODEL, D_FF);
    prep_w<<<dim3(D_MODEL / 32, D_FF / 32), 256>>>(w_ff2, w_ff2_t, D_FF, D_MODEL);

    // 1. LN1 -> fp16
    ln_half<<<ROWS, 256>>>(x, ln1_g, ln1_b, h);

    // 2. QKV projection -> fp16
    gemm_mma<3><<<dim3(3 * D_MODEL / 128, ROWS / 128), 256, GEMM_SMEM>>>(
        h, w_qkv_t, b_qkv, nullptr, nullptr, qkvh, ROWS, 3 * D_MODEL, D_MODEL);

    // 3. tensor-core attention -> fp16 ctx
    attn_mma<<<dim3(SEQ / 64, NH, BATCH), 256, ATT_SMEM>>>(qkvh, ctx);

    // 4. out-projection + residual -> fp32 x2
    gemm_mma<1><<<dim3(D_MODEL / 128, ROWS / 128), 256, GEMM_SMEM>>>(
        ctx, w_out_t, b_out, x, x2, nullptr, ROWS, D_MODEL, D_MODEL);

    // 5. LN2 -> fp16
    ln_half<<<ROWS, 256>>>(x2, ln2_g, ln2_b, h);

    // 6. FF1 + gelu -> fp16
    gemm_mma<2><<<dim3(D_FF / 128, ROWS / 128), 256, GEMM_SMEM>>>(
        h, w_ff1_t, b_ff1, nullptr, nullptr, ff, ROWS, D_FF, D_MODEL);

    // 7. FF2 + residual -> output
    gemm_mma<1><<<dim3(D_MODEL / 128, ROWS / 128), 256, GEMM_SMEM>>>(
        ff, w_ff2_t, b_ff2, x2, out, nullptr, ROWS, D_MODEL, D_FF);
}